// round 2
// baseline (speedup 1.0000x reference)
#include <cuda_runtime.h>
#include <math.h>

#define B_   8
#define S_   1024
#define D_   1152
#define H_   16
#define HD_  72
#define M_   (B_*S_)          // 8192 rows
#define N3_  (3*D_)           // 3456
#define BHSHD (B_*H_*S_*HD_)  // 9437184

// Scratch (no allocations allowed — device globals)
__device__ float g_qkv[3u*BHSHD];   // [3][B][H][S][HD]
__device__ float g_attn[(size_t)M_*D_]; // [B][S][D] attention output (pre-proj)

// ---------------------------------------------------------------------------
// NT GEMM: C[m,n] = sum_k A[m,k] * W[n,k] + bias[n]
// BM=BN=64, BK=16, 256 threads, 4x4 microtile per thread.
// MODE 0: plain write to C[m*N+n]  (projection)
// MODE 1: scatter into g_qkv [3][B][H][S][HD] (QKV)
// ---------------------------------------------------------------------------
template <int MODE>
__global__ __launch_bounds__(256)
void gemm_nt(const float* __restrict__ A,
             const float* __restrict__ W,
             const float* __restrict__ bias,
             float* __restrict__ C,
             int K, int N)
{
    const int BM = 64, BN = 64, BK = 16;
    __shared__ float As[BK][BM];
    __shared__ float Ws[BK][BN];

    const int tid = threadIdx.x;
    const int bm0 = blockIdx.y * BM;
    const int bn0 = blockIdx.x * BN;
    const int tx = tid & 15;        // 0..15 -> 4 cols each
    const int ty = tid >> 4;        // 0..15 -> 4 rows each
    const int lrow = tid >> 2;      // 0..63
    const int lc4  = (tid & 3) * 4; // 0,4,8,12

    const float* Ain = (MODE == 0) ? g_attn : A;

    float acc[4][4];
#pragma unroll
    for (int i = 0; i < 4; i++)
#pragma unroll
        for (int j = 0; j < 4; j++) acc[i][j] = 0.f;

    for (int k0 = 0; k0 < K; k0 += BK) {
        float4 av = *(const float4*)&Ain[(size_t)(bm0 + lrow) * K + k0 + lc4];
        float4 wv = *(const float4*)&W  [(size_t)(bn0 + lrow) * K + k0 + lc4];
        __syncthreads();
        As[lc4+0][lrow] = av.x; As[lc4+1][lrow] = av.y;
        As[lc4+2][lrow] = av.z; As[lc4+3][lrow] = av.w;
        Ws[lc4+0][lrow] = wv.x; Ws[lc4+1][lrow] = wv.y;
        Ws[lc4+2][lrow] = wv.z; Ws[lc4+3][lrow] = wv.w;
        __syncthreads();
#pragma unroll
        for (int k = 0; k < BK; k++) {
            float4 a = *(const float4*)&As[k][ty * 4];
            float4 w = *(const float4*)&Ws[k][tx * 4];
            acc[0][0] += a.x * w.x; acc[0][1] += a.x * w.y; acc[0][2] += a.x * w.z; acc[0][3] += a.x * w.w;
            acc[1][0] += a.y * w.x; acc[1][1] += a.y * w.y; acc[1][2] += a.y * w.z; acc[1][3] += a.y * w.w;
            acc[2][0] += a.z * w.x; acc[2][1] += a.z * w.y; acc[2][2] += a.z * w.z; acc[2][3] += a.z * w.w;
            acc[3][0] += a.w * w.x; acc[3][1] += a.w * w.y; acc[3][2] += a.w * w.z; acc[3][3] += a.w * w.w;
        }
    }

#pragma unroll
    for (int i = 0; i < 4; i++) {
        const int m = bm0 + ty * 4 + i;
#pragma unroll
        for (int j = 0; j < 4; j++) {
            const int n = bn0 + tx * 4 + j;
            const float v = acc[i][j] + bias[n];
            if (MODE == 0) {
                C[(size_t)m * N + n] = v;
            } else {
                const int b = m >> 10, s = m & 1023;
                const int t = n / D_;
                const int r = n - t * D_;
                const int h = r / HD_;
                const int hd = r - h * HD_;
                g_qkv[(((size_t)(t * B_ + b) * H_ + h) * S_ + s) * HD_ + hd] = v;
            }
        }
    }
}

// ---------------------------------------------------------------------------
// RoPE on q and k halves of g_qkv. One thread per (row, i<36) pair.
// rows cover [2][B][H][S]; layout of g_qkv is [t][b][h][s][hd].
// ---------------------------------------------------------------------------
__global__ void rope_kernel(const float* __restrict__ cosp,
                            const float* __restrict__ sinp)
{
    const int total = 2 * B_ * H_ * S_ * 36;
    int idx = blockIdx.x * blockDim.x + threadIdx.x;
    if (idx >= total) return;
    const int i = idx % 36;
    const int row = idx / 36;          // over [t<2][b][h][s]
    const int s = row & (S_ - 1);
    float* base = g_qkv + (size_t)row * HD_;
    const float x1 = base[i];
    const float x2 = base[i + 36];
    const float c1 = cosp[s * HD_ + i];
    const float n1 = sinp[s * HD_ + i];
    const float c2 = cosp[s * HD_ + i + 36];
    const float n2 = sinp[s * HD_ + i + 36];
    base[i]      = x1 * c1 - x2 * n1;
    base[i + 36] = x2 * c2 + x1 * n2;
}

// ---------------------------------------------------------------------------
// Attention: block = (bh, 128-query tile). 128 threads, 1 query row/thread.
// K/V tiles of 32 rows staged in smem (broadcast reads across the warp).
// Online softmax with rescale-on-new-max. Output -> g_attn [b][s][h*HD+hd].
// ---------------------------------------------------------------------------
#define KT 32
__global__ __launch_bounds__(128, 2)
void attn_kernel()
{
    __shared__ float Ks[KT][HD_];
    __shared__ float Vs[KT][HD_];

    const int bh = blockIdx.x;                 // 0..127  (b*H + h)
    const int q0 = blockIdx.y * 128;
    const int t  = threadIdx.x;
    const int b  = bh >> 4, h = bh & 15;

    const float* gq = g_qkv;
    const float* gk = g_qkv + (size_t)BHSHD;
    const float* gv = g_qkv + (size_t)2 * BHSHD;

    const float* qrow = gq + ((size_t)bh * S_ + q0 + t) * HD_;
    float4 q4[18];
#pragma unroll
    for (int i = 0; i < 18; i++) q4[i] = *(const float4*)&qrow[i * 4];

    float4 o4[18];
#pragma unroll
    for (int i = 0; i < 18; i++) { o4[i].x = 0.f; o4[i].y = 0.f; o4[i].z = 0.f; o4[i].w = 0.f; }

    float m = -1e30f, l = 0.f;
    const float scale = 0.1178511301977579f;   // 72^-0.5

    for (int j0 = 0; j0 < S_; j0 += KT) {
        __syncthreads();
        const size_t kb = ((size_t)bh * S_ + j0) * HD_;
        for (int idx = t; idx < KT * HD_; idx += 128) {
            ((float*)Ks)[idx] = gk[kb + idx];
            ((float*)Vs)[idx] = gv[kb + idx];
        }
        __syncthreads();

        for (int j = 0; j < KT; j++) {
            const float4* kr = (const float4*)&Ks[j][0];
            float s0 = 0.f, s1 = 0.f, s2 = 0.f, s3 = 0.f;
#pragma unroll
            for (int i = 0; i < 18; i++) {
                float4 kv = kr[i];
                s0 += q4[i].x * kv.x; s1 += q4[i].y * kv.y;
                s2 += q4[i].z * kv.z; s3 += q4[i].w * kv.w;
            }
            const float sc = (s0 + s1) + (s2 + s3);
            const float sv = sc * scale;
            if (sv > m) {
                const float c = __expf(m - sv);
#pragma unroll
                for (int i = 0; i < 18; i++) {
                    o4[i].x *= c; o4[i].y *= c; o4[i].z *= c; o4[i].w *= c;
                }
                l *= c;
                m = sv;
            }
            const float p = __expf(sv - m);
            l += p;
            const float4* vr = (const float4*)&Vs[j][0];
#pragma unroll
            for (int i = 0; i < 18; i++) {
                float4 vv = vr[i];
                o4[i].x += p * vv.x; o4[i].y += p * vv.y;
                o4[i].z += p * vv.z; o4[i].w += p * vv.w;
            }
        }
    }

    const float inv = 1.f / l;
    float* dst = g_attn + ((size_t)(b * S_ + q0 + t) * D_ + h * HD_);
#pragma unroll
    for (int i = 0; i < 18; i++) {
        float4 ov;
        ov.x = o4[i].x * inv; ov.y = o4[i].y * inv;
        ov.z = o4[i].z * inv; ov.w = o4[i].w * inv;
        *(float4*)&dst[i * 4] = ov;
    }
}

// ---------------------------------------------------------------------------
// Launch
// inputs (metadata order): hidden_states, cos, sin, qkv_w, qkv_b, proj_w, proj_b
// ---------------------------------------------------------------------------
extern "C" void kernel_launch(void* const* d_in, const int* in_sizes, int n_in,
                              void* d_out, int out_size)
{
    const float* hidden = (const float*)d_in[0];
    const float* cosp   = (const float*)d_in[1];
    const float* sinp   = (const float*)d_in[2];
    const float* qkv_w  = (const float*)d_in[3];
    const float* qkv_b  = (const float*)d_in[4];
    const float* proj_w = (const float*)d_in[5];
    const float* proj_b = (const float*)d_in[6];
    float* out = (float*)d_out;

    // 1) QKV GEMM with scatter into [3][B][H][S][HD]
    {
        dim3 grid(N3_ / 64, M_ / 64);
        gemm_nt<1><<<grid, 256>>>(hidden, qkv_w, qkv_b, nullptr, D_, N3_);
    }
    // 2) RoPE on q and k
    {
        const int total = 2 * B_ * H_ * S_ * 36;
        rope_kernel<<<(total + 255) / 256, 256>>>(cosp, sinp);
    }
    // 3) Attention
    {
        dim3 grid(B_ * H_, S_ / 128);
        attn_kernel<<<grid, 128>>>();
    }
    // 4) Output projection
    {
        dim3 grid(D_ / 64, M_ / 64);
        gemm_nt<0><<<grid, 256>>>(nullptr, proj_w, proj_b, out, D_, D_);
    }
}

// round 4
// speedup vs baseline: 1.5476x; 1.5476x over previous
#include <cuda_runtime.h>
#include <cuda_bf16.h>
#include <math.h>
#include <stdint.h>

#define B_   8
#define S_   1024
#define D_   1152
#define H_   16
#define HD_  72
#define M_   (B_*S_)          // 8192
#define N3_  (3*D_)           // 3456
#define BHSHD (B_*H_*S_*HD_)  // 9437184

// Scratch (no allocations allowed — device globals)
__device__ float g_qkv[3u*BHSHD];        // [3][B][H][S][HD]
__device__ float g_attn[(size_t)M_*D_];  // [B][S][D]

// ---------------------------------------------------------------------------
// fp32 -> (hi, lo) bf16 split
// ---------------------------------------------------------------------------
__device__ __forceinline__ void cvt_hi_lo(float4 v, uint2& hi, uint2& lo) {
    __nv_bfloat16 hx = __float2bfloat16(v.x), hy = __float2bfloat16(v.y);
    __nv_bfloat16 hz = __float2bfloat16(v.z), hw = __float2bfloat16(v.w);
    __nv_bfloat16 lx = __float2bfloat16(v.x - __bfloat162float(hx));
    __nv_bfloat16 ly = __float2bfloat16(v.y - __bfloat162float(hy));
    __nv_bfloat16 lz = __float2bfloat16(v.z - __bfloat162float(hz));
    __nv_bfloat16 lw = __float2bfloat16(v.w - __bfloat162float(hw));
    hi.x = (uint32_t)__bfloat16_as_ushort(hx) | ((uint32_t)__bfloat16_as_ushort(hy) << 16);
    hi.y = (uint32_t)__bfloat16_as_ushort(hz) | ((uint32_t)__bfloat16_as_ushort(hw) << 16);
    lo.x = (uint32_t)__bfloat16_as_ushort(lx) | ((uint32_t)__bfloat16_as_ushort(ly) << 16);
    lo.y = (uint32_t)__bfloat16_as_ushort(lz) | ((uint32_t)__bfloat16_as_ushort(lw) << 16);
}

__device__ __forceinline__ void mma16816(float* c, const uint32_t* a, const uint32_t* b) {
    asm volatile(
        "mma.sync.aligned.m16n8k16.row.col.f32.bf16.bf16.f32 "
        "{%0,%1,%2,%3}, {%4,%5,%6,%7}, {%8,%9}, {%0,%1,%2,%3};"
        : "+f"(c[0]), "+f"(c[1]), "+f"(c[2]), "+f"(c[3])
        : "r"(a[0]), "r"(a[1]), "r"(a[2]), "r"(a[3]), "r"(b[0]), "r"(b[1]));
}

// ---------------------------------------------------------------------------
// bf16-split HMMA GEMM: C[m,n] = sum_k A[m,k]*W[n,k] + bias[n]
// BM=128, BN=128, BK=32. 256 threads (8 warps, 2x4), warp tile 64x32.
// MODE 0: plain write to C (proj, A = g_attn). MODE 1: scatter into g_qkv.
// ---------------------------------------------------------------------------
#define SKP 36   // padded smem row stride in bf16 elements (72B)

template <int MODE>
__global__ __launch_bounds__(256)
void gemm_mma(const float* __restrict__ A,
              const float* __restrict__ W,
              const float* __restrict__ bias,
              float* __restrict__ C,
              int K, int N)
{
    __shared__ __nv_bfloat16 sAh[128 * SKP], sAl[128 * SKP];
    __shared__ __nv_bfloat16 sBh[128 * SKP], sBl[128 * SKP];

    const int tid = threadIdx.x, wid = tid >> 5, lane = tid & 31;
    const int bm0 = blockIdx.y * 128, bn0 = blockIdx.x * 128;
    const int wm = (wid >> 2) * 64, wn = (wid & 3) * 32;
    const float* Ain = (MODE == 0) ? g_attn : A;

    float acc[4][4][4];
#pragma unroll
    for (int mt = 0; mt < 4; mt++)
#pragma unroll
        for (int nt = 0; nt < 4; nt++)
#pragma unroll
            for (int r = 0; r < 4; r++) acc[mt][nt][r] = 0.f;

    const int arow = tid >> 3;        // 0..31 (+j*32)
    const int acol = (tid & 7) * 4;   // 0,4,...,28

    float4 av[4], bv[4];
    // Prologue: global loads for chunk 0
#pragma unroll
    for (int j = 0; j < 4; j++) {
        const int r = arow + j * 32;
        av[j] = *(const float4*)&Ain[(size_t)(bm0 + r) * K + acol];
        bv[j] = *(const float4*)&W  [(size_t)(bn0 + r) * K + acol];
    }

    const int NCH = K / 32;
    for (int c = 0; c < NCH; c++) {
        __syncthreads();
#pragma unroll
        for (int j = 0; j < 4; j++) {
            const int r = arow + j * 32;
            uint2 hi, lo;
            cvt_hi_lo(av[j], hi, lo);
            *(uint2*)&sAh[r * SKP + acol] = hi;
            *(uint2*)&sAl[r * SKP + acol] = lo;
            cvt_hi_lo(bv[j], hi, lo);
            *(uint2*)&sBh[r * SKP + acol] = hi;
            *(uint2*)&sBl[r * SKP + acol] = lo;
        }
        __syncthreads();

        if (c + 1 < NCH) {
            const int k0 = (c + 1) * 32;
#pragma unroll
            for (int j = 0; j < 4; j++) {
                const int r = arow + j * 32;
                av[j] = *(const float4*)&Ain[(size_t)(bm0 + r) * K + k0 + acol];
                bv[j] = *(const float4*)&W  [(size_t)(bn0 + r) * K + k0 + acol];
            }
        }

#pragma unroll
        for (int ks = 0; ks < 2; ks++) {
            const int k0 = ks * 16 + (lane & 3) * 2;
            const int g  = lane >> 2;
            uint32_t ah[4][4], al[4][4];
#pragma unroll
            for (int mt = 0; mt < 4; mt++) {
                const int row = wm + mt * 16 + g;
                ah[mt][0] = *(const uint32_t*)&sAh[row * SKP + k0];
                ah[mt][1] = *(const uint32_t*)&sAh[(row + 8) * SKP + k0];
                ah[mt][2] = *(const uint32_t*)&sAh[row * SKP + k0 + 8];
                ah[mt][3] = *(const uint32_t*)&sAh[(row + 8) * SKP + k0 + 8];
                al[mt][0] = *(const uint32_t*)&sAl[row * SKP + k0];
                al[mt][1] = *(const uint32_t*)&sAl[(row + 8) * SKP + k0];
                al[mt][2] = *(const uint32_t*)&sAl[row * SKP + k0 + 8];
                al[mt][3] = *(const uint32_t*)&sAl[(row + 8) * SKP + k0 + 8];
            }
            uint32_t bh[4][2], bl[4][2];
#pragma unroll
            for (int nt = 0; nt < 4; nt++) {
                const int col = wn + nt * 8 + g;
                bh[nt][0] = *(const uint32_t*)&sBh[col * SKP + k0];
                bh[nt][1] = *(const uint32_t*)&sBh[col * SKP + k0 + 8];
                bl[nt][0] = *(const uint32_t*)&sBl[col * SKP + k0];
                bl[nt][1] = *(const uint32_t*)&sBl[col * SKP + k0 + 8];
            }
#pragma unroll
            for (int mt = 0; mt < 4; mt++)
#pragma unroll
                for (int nt = 0; nt < 4; nt++) {
                    mma16816(acc[mt][nt], ah[mt], bh[nt]);
                    mma16816(acc[mt][nt], ah[mt], bl[nt]);
                    mma16816(acc[mt][nt], al[mt], bh[nt]);
                }
        }
    }

    // Epilogue
    const int g = lane >> 2, tg = (lane & 3) * 2;
#pragma unroll
    for (int mt = 0; mt < 4; mt++) {
#pragma unroll
        for (int nt = 0; nt < 4; nt++) {
#pragma unroll
            for (int r = 0; r < 4; r++) {
                const int m = bm0 + wm + mt * 16 + g + (r >= 2 ? 8 : 0);
                const int n = bn0 + wn + nt * 8 + tg + (r & 1);
                const float v = acc[mt][nt][r] + bias[n];
                if (MODE == 0) {
                    C[(size_t)m * N + n] = v;
                } else {
                    const int b = m >> 10, s = m & 1023;
                    const int t = n / D_;
                    const int rr = n - t * D_;
                    const int h = rr / HD_;
                    const int hd = rr - h * HD_;
                    g_qkv[(((size_t)(t * B_ + b) * H_ + h) * S_ + s) * HD_ + hd] = v;
                }
            }
        }
    }
}

// ---------------------------------------------------------------------------
// RoPE on q and k halves of g_qkv
// ---------------------------------------------------------------------------
__global__ void rope_kernel(const float* __restrict__ cosp,
                            const float* __restrict__ sinp)
{
    const int total = 2 * B_ * H_ * S_ * 36;
    int idx = blockIdx.x * blockDim.x + threadIdx.x;
    if (idx >= total) return;
    const int i = idx % 36;
    const int row = idx / 36;
    const int s = row & (S_ - 1);
    float* base = g_qkv + (size_t)row * HD_;
    const float x1 = base[i];
    const float x2 = base[i + 36];
    const float c1 = cosp[s * HD_ + i];
    const float n1 = sinp[s * HD_ + i];
    const float c2 = cosp[s * HD_ + i + 36];
    const float n2 = sinp[s * HD_ + i + 36];
    base[i]      = x1 * c1 - x2 * n1;
    base[i + 36] = x2 * c2 + x1 * n2;
}

// ---------------------------------------------------------------------------
// Attention: block=(bh, 128-query tile), online softmax (unchanged)
// ---------------------------------------------------------------------------
#define KT 32
__global__ __launch_bounds__(128, 2)
void attn_kernel()
{
    __shared__ float Ks[KT][HD_];
    __shared__ float Vs[KT][HD_];

    const int bh = blockIdx.x;
    const int q0 = blockIdx.y * 128;
    const int t  = threadIdx.x;
    const int b  = bh >> 4, h = bh & 15;

    const float* gk = g_qkv + (size_t)BHSHD;
    const float* gv = g_qkv + (size_t)2 * BHSHD;

    const float* qrow = g_qkv + ((size_t)bh * S_ + q0 + t) * HD_;
    float4 q4[18];
#pragma unroll
    for (int i = 0; i < 18; i++) q4[i] = *(const float4*)&qrow[i * 4];

    float4 o4[18];
#pragma unroll
    for (int i = 0; i < 18; i++) { o4[i].x = 0.f; o4[i].y = 0.f; o4[i].z = 0.f; o4[i].w = 0.f; }

    float m = -1e30f, l = 0.f;
    const float scale = 0.1178511301977579f;

    for (int j0 = 0; j0 < S_; j0 += KT) {
        __syncthreads();
        const size_t kb = ((size_t)bh * S_ + j0) * HD_;
        for (int idx = t; idx < KT * HD_; idx += 128) {
            ((float*)Ks)[idx] = gk[kb + idx];
            ((float*)Vs)[idx] = gv[kb + idx];
        }
        __syncthreads();

        for (int j = 0; j < KT; j++) {
            const float4* kr = (const float4*)&Ks[j][0];
            float s0 = 0.f, s1 = 0.f, s2 = 0.f, s3 = 0.f;
#pragma unroll
            for (int i = 0; i < 18; i++) {
                float4 kv = kr[i];
                s0 += q4[i].x * kv.x; s1 += q4[i].y * kv.y;
                s2 += q4[i].z * kv.z; s3 += q4[i].w * kv.w;
            }
            const float sv = ((s0 + s1) + (s2 + s3)) * scale;
            if (sv > m) {
                const float c = __expf(m - sv);
#pragma unroll
                for (int i = 0; i < 18; i++) {
                    o4[i].x *= c; o4[i].y *= c; o4[i].z *= c; o4[i].w *= c;
                }
                l *= c;
                m = sv;
            }
            const float p = __expf(sv - m);
            l += p;
            const float4* vr = (const float4*)&Vs[j][0];
#pragma unroll
            for (int i = 0; i < 18; i++) {
                float4 vv = vr[i];
                o4[i].x += p * vv.x; o4[i].y += p * vv.y;
                o4[i].z += p * vv.z; o4[i].w += p * vv.w;
            }
        }
    }

    const float inv = 1.f / l;
    float* dst = g_attn + ((size_t)(b * S_ + q0 + t) * D_ + h * HD_);
#pragma unroll
    for (int i = 0; i < 18; i++) {
        float4 ov;
        ov.x = o4[i].x * inv; ov.y = o4[i].y * inv;
        ov.z = o4[i].z * inv; ov.w = o4[i].w * inv;
        *(float4*)&dst[i * 4] = ov;
    }
}

// ---------------------------------------------------------------------------
// Launch
// ---------------------------------------------------------------------------
extern "C" void kernel_launch(void* const* d_in, const int* in_sizes, int n_in,
                              void* d_out, int out_size)
{
    const float* hidden = (const float*)d_in[0];
    const float* cosp   = (const float*)d_in[1];
    const float* sinp   = (const float*)d_in[2];
    const float* qkv_w  = (const float*)d_in[3];
    const float* qkv_b  = (const float*)d_in[4];
    const float* proj_w = (const float*)d_in[5];
    const float* proj_b = (const float*)d_in[6];
    float* out = (float*)d_out;

    // 1) QKV GEMM (HMMA bf16-split) with scatter into [3][B][H][S][HD]
    {
        dim3 grid(N3_ / 128, M_ / 128);
        gemm_mma<1><<<grid, 256>>>(hidden, qkv_w, qkv_b, nullptr, D_, N3_);
    }
    // 2) RoPE on q and k
    {
        const int total = 2 * B_ * H_ * S_ * 36;
        rope_kernel<<<(total + 255) / 256, 256>>>(cosp, sinp);
    }
    // 3) Attention
    {
        dim3 grid(B_ * H_, S_ / 128);
        attn_kernel<<<grid, 128>>>();
    }
    // 4) Output projection (HMMA bf16-split)
    {
        dim3 grid(D_ / 128, M_ / 128);
        gemm_mma<0><<<grid, 256>>>(nullptr, proj_w, proj_b, out, D_, D_);
    }
}

// round 5
// speedup vs baseline: 2.2130x; 1.4300x over previous
#include <cuda_runtime.h>
#include <cuda_bf16.h>
#include <math.h>
#include <stdint.h>

#define B_   8
#define S_   1024
#define D_   1152
#define H_   16
#define HD_  72
#define M_   (B_*S_)          // 8192
#define N3_  (3*D_)           // 3456
#define BHSHD (B_*H_*S_*HD_)  // 9437184

// Scratch (no allocations allowed — device globals)
__device__ float g_qkv[3u*BHSHD];        // [3][B][H][S][HD]
__device__ float g_attn[(size_t)M_*D_];  // [B][S][D]

// ---------------------------------------------------------------------------
// helpers
// ---------------------------------------------------------------------------
__device__ __forceinline__ uint32_t pk(__nv_bfloat16 a, __nv_bfloat16 b) {
    return (uint32_t)__bfloat16_as_ushort(a) | ((uint32_t)__bfloat16_as_ushort(b) << 16);
}
__device__ __forceinline__ void cvt_hi_lo(float4 v, uint2& hi, uint2& lo) {
    __nv_bfloat16 hx = __float2bfloat16(v.x), hy = __float2bfloat16(v.y);
    __nv_bfloat16 hz = __float2bfloat16(v.z), hw = __float2bfloat16(v.w);
    __nv_bfloat16 lx = __float2bfloat16(v.x - __bfloat162float(hx));
    __nv_bfloat16 ly = __float2bfloat16(v.y - __bfloat162float(hy));
    __nv_bfloat16 lz = __float2bfloat16(v.z - __bfloat162float(hz));
    __nv_bfloat16 lw = __float2bfloat16(v.w - __bfloat162float(hw));
    hi.x = pk(hx, hy); hi.y = pk(hz, hw);
    lo.x = pk(lx, ly); lo.y = pk(lz, lw);
}
__device__ __forceinline__ void mma16816(float* c, const uint32_t* a, const uint32_t* b) {
    asm volatile(
        "mma.sync.aligned.m16n8k16.row.col.f32.bf16.bf16.f32 "
        "{%0,%1,%2,%3}, {%4,%5,%6,%7}, {%8,%9}, {%0,%1,%2,%3};"
        : "+f"(c[0]), "+f"(c[1]), "+f"(c[2]), "+f"(c[3])
        : "r"(a[0]), "r"(a[1]), "r"(a[2]), "r"(a[3]), "r"(b[0]), "r"(b[1]));
}
// FMA-pipe 2^x for x <= 0 (no MUFU): magic-round + deg-4 Taylor + exp-bit add
__device__ __forceinline__ float exp2p(float d) {
    d = fmaxf(d, -100.f);
    const float MAGIC = 12582912.f;       // 1.5 * 2^23
    float frnd = d + MAGIC;
    int   i    = __float_as_int(frnd) - __float_as_int(MAGIC);
    float f    = d - (frnd - MAGIC);      // [-0.5, 0.5]
    float y = 9.6181e-3f;
    y = fmaf(y, f, 5.54906e-2f);
    y = fmaf(y, f, 2.402265e-1f);
    y = fmaf(y, f, 6.931472e-1f);
    y = fmaf(y, f, 1.f);
    return __int_as_float(__float_as_int(y) + (i << 23));
}

// ---------------------------------------------------------------------------
// bf16-split HMMA GEMM (unchanged from R4)
// ---------------------------------------------------------------------------
#define SKP 36

template <int MODE>
__global__ __launch_bounds__(256)
void gemm_mma(const float* __restrict__ A,
              const float* __restrict__ W,
              const float* __restrict__ bias,
              float* __restrict__ C,
              int K, int N)
{
    __shared__ __nv_bfloat16 sAh[128 * SKP], sAl[128 * SKP];
    __shared__ __nv_bfloat16 sBh[128 * SKP], sBl[128 * SKP];

    const int tid = threadIdx.x, wid = tid >> 5, lane = tid & 31;
    const int bm0 = blockIdx.y * 128, bn0 = blockIdx.x * 128;
    const int wm = (wid >> 2) * 64, wn = (wid & 3) * 32;
    const float* Ain = (MODE == 0) ? g_attn : A;

    float acc[4][4][4];
#pragma unroll
    for (int mt = 0; mt < 4; mt++)
#pragma unroll
        for (int nt = 0; nt < 4; nt++)
#pragma unroll
            for (int r = 0; r < 4; r++) acc[mt][nt][r] = 0.f;

    const int arow = tid >> 3;
    const int acol = (tid & 7) * 4;

    float4 av[4], bv[4];
#pragma unroll
    for (int j = 0; j < 4; j++) {
        const int r = arow + j * 32;
        av[j] = *(const float4*)&Ain[(size_t)(bm0 + r) * K + acol];
        bv[j] = *(const float4*)&W  [(size_t)(bn0 + r) * K + acol];
    }

    const int NCH = K / 32;
    for (int c = 0; c < NCH; c++) {
        __syncthreads();
#pragma unroll
        for (int j = 0; j < 4; j++) {
            const int r = arow + j * 32;
            uint2 hi, lo;
            cvt_hi_lo(av[j], hi, lo);
            *(uint2*)&sAh[r * SKP + acol] = hi;
            *(uint2*)&sAl[r * SKP + acol] = lo;
            cvt_hi_lo(bv[j], hi, lo);
            *(uint2*)&sBh[r * SKP + acol] = hi;
            *(uint2*)&sBl[r * SKP + acol] = lo;
        }
        __syncthreads();

        if (c + 1 < NCH) {
            const int k0 = (c + 1) * 32;
#pragma unroll
            for (int j = 0; j < 4; j++) {
                const int r = arow + j * 32;
                av[j] = *(const float4*)&Ain[(size_t)(bm0 + r) * K + k0 + acol];
                bv[j] = *(const float4*)&W  [(size_t)(bn0 + r) * K + k0 + acol];
            }
        }

#pragma unroll
        for (int ks = 0; ks < 2; ks++) {
            const int k0 = ks * 16 + (lane & 3) * 2;
            const int g  = lane >> 2;
            uint32_t ah[4][4], al[4][4];
#pragma unroll
            for (int mt = 0; mt < 4; mt++) {
                const int row = wm + mt * 16 + g;
                ah[mt][0] = *(const uint32_t*)&sAh[row * SKP + k0];
                ah[mt][1] = *(const uint32_t*)&sAh[(row + 8) * SKP + k0];
                ah[mt][2] = *(const uint32_t*)&sAh[row * SKP + k0 + 8];
                ah[mt][3] = *(const uint32_t*)&sAh[(row + 8) * SKP + k0 + 8];
                al[mt][0] = *(const uint32_t*)&sAl[row * SKP + k0];
                al[mt][1] = *(const uint32_t*)&sAl[(row + 8) * SKP + k0];
                al[mt][2] = *(const uint32_t*)&sAl[row * SKP + k0 + 8];
                al[mt][3] = *(const uint32_t*)&sAl[(row + 8) * SKP + k0 + 8];
            }
            uint32_t bh[4][2], bl[4][2];
#pragma unroll
            for (int nt = 0; nt < 4; nt++) {
                const int col = wn + nt * 8 + g;
                bh[nt][0] = *(const uint32_t*)&sBh[col * SKP + k0];
                bh[nt][1] = *(const uint32_t*)&sBh[col * SKP + k0 + 8];
                bl[nt][0] = *(const uint32_t*)&sBl[col * SKP + k0];
                bl[nt][1] = *(const uint32_t*)&sBl[col * SKP + k0 + 8];
            }
#pragma unroll
            for (int mt = 0; mt < 4; mt++)
#pragma unroll
                for (int nt = 0; nt < 4; nt++) {
                    mma16816(acc[mt][nt], ah[mt], bh[nt]);
                    mma16816(acc[mt][nt], ah[mt], bl[nt]);
                    mma16816(acc[mt][nt], al[mt], bh[nt]);
                }
        }
    }

    const int g = lane >> 2, tg = (lane & 3) * 2;
#pragma unroll
    for (int mt = 0; mt < 4; mt++) {
#pragma unroll
        for (int nt = 0; nt < 4; nt++) {
#pragma unroll
            for (int r = 0; r < 4; r++) {
                const int m = bm0 + wm + mt * 16 + g + (r >= 2 ? 8 : 0);
                const int n = bn0 + wn + nt * 8 + tg + (r & 1);
                const float v = acc[mt][nt][r] + bias[n];
                if (MODE == 0) {
                    C[(size_t)m * N + n] = v;
                } else {
                    const int b = m >> 10, s = m & 1023;
                    const int t = n / D_;
                    const int rr = n - t * D_;
                    const int h = rr / HD_;
                    const int hd = rr - h * HD_;
                    g_qkv[(((size_t)(t * B_ + b) * H_ + h) * S_ + s) * HD_ + hd] = v;
                }
            }
        }
    }
}

// ---------------------------------------------------------------------------
// RoPE (unchanged)
// ---------------------------------------------------------------------------
__global__ void rope_kernel(const float* __restrict__ cosp,
                            const float* __restrict__ sinp)
{
    const int total = 2 * B_ * H_ * S_ * 36;
    int idx = blockIdx.x * blockDim.x + threadIdx.x;
    if (idx >= total) return;
    const int i = idx % 36;
    const int row = idx / 36;
    const int s = row & (S_ - 1);
    float* base = g_qkv + (size_t)row * HD_;
    const float x1 = base[i];
    const float x2 = base[i + 36];
    base[i]      = x1 * cosp[s * HD_ + i]      - x2 * sinp[s * HD_ + i];
    base[i + 36] = x2 * cosp[s * HD_ + i + 36] + x1 * sinp[s * HD_ + i + 36];
}

// ---------------------------------------------------------------------------
// HMMA flash attention.
// CTA = (bh, 128-q tile), 256 thr (8 warps x 16 q-rows). K-tiles of 64 keys.
// Q pre-scaled by 72^-0.5 * log2(e); softmax in base 2 via FMA-only exp2p.
// 3-term bf16 split on QK^T and PV. P formed in registers from S C-frags.
// ---------------------------------------------------------------------------
#define SCL 0.170044411294f   // 72^-0.5 * log2(e)

__global__ __launch_bounds__(256)
void attn_mma()
{
    __shared__ __nv_bfloat16 sm[20480];           // 40 KB
    __nv_bfloat16* Qh = sm;                       // 128 x 80
    __nv_bfloat16* Ql = sm + 10240;
    __nv_bfloat16* Kh = sm;                       // 64 x 80   (reuses Q region)
    __nv_bfloat16* Kl = sm + 5120;
    __nv_bfloat16* Vh = sm + 10240;               // 72 x 68   (transposed [d][key])
    __nv_bfloat16* Vl = sm + 15136;

    const int tid = threadIdx.x, w = tid >> 5, lane = tid & 31;
    const int g = lane >> 2, tg = (lane & 3) * 2;
    const int bh = blockIdx.x, q0 = blockIdx.y * 128;
    const int b = bh >> 4, h = bh & 15;
    const float* gq = g_qkv;
    const float* gk = g_qkv + (size_t)BHSHD;
    const float* gv = g_qkv + (size_t)2 * BHSHD;

    // ---- stage Q (scaled) as hi/lo bf16, zero-padded d 72..79 ----
    for (int i = tid; i < 128 * 20; i += 256) {
        const int row = i / 20, c4 = (i % 20) * 4;
        float4 v = make_float4(0.f, 0.f, 0.f, 0.f);
        if (c4 < 72)
            v = *(const float4*)&gq[((size_t)(bh << 10) + q0 + row) * HD_ + c4];
        v.x *= SCL; v.y *= SCL; v.z *= SCL; v.w *= SCL;
        uint2 hi, lo; cvt_hi_lo(v, hi, lo);
        *(uint2*)&Qh[row * 80 + c4] = hi;
        *(uint2*)&Ql[row * 80 + c4] = lo;
    }
    __syncthreads();

    // ---- Q fragments to registers ----
    uint32_t qh[5][4], ql[5][4];
    const int qrow = w * 16 + g;
#pragma unroll
    for (int c = 0; c < 5; c++) {
        const int base = qrow * 80 + c * 16 + tg;
        qh[c][0] = *(const uint32_t*)&Qh[base];
        qh[c][1] = *(const uint32_t*)&Qh[base + 8 * 80];
        qh[c][2] = *(const uint32_t*)&Qh[base + 8];
        qh[c][3] = *(const uint32_t*)&Qh[base + 8 * 80 + 8];
        ql[c][0] = *(const uint32_t*)&Ql[base];
        ql[c][1] = *(const uint32_t*)&Ql[base + 8 * 80];
        ql[c][2] = *(const uint32_t*)&Ql[base + 8];
        ql[c][3] = *(const uint32_t*)&Ql[base + 8 * 80 + 8];
    }
    __syncthreads();

    // ---- zero K pad columns d 72..79 (written once, loop never touches) ----
    for (int i = tid; i < 512; i += 256) {
        const int arr = i >> 8, key = (i >> 2) & 63, c2 = (i & 3) * 2;
        *(uint32_t*)&((arr ? Kl : Kh)[key * 80 + 72 + c2]) = 0u;
    }

    float o[9][4];
#pragma unroll
    for (int n = 0; n < 9; n++) { o[n][0] = 0.f; o[n][1] = 0.f; o[n][2] = 0.f; o[n][3] = 0.f; }
    float mr0 = -1e30f, mr1 = -1e30f, lr0 = 0.f, lr1 = 0.f;

    for (int j0 = 0; j0 < S_; j0 += 64) {
        // ---- load K tile (hi/lo) and V tile transposed (hi/lo) ----
        for (int i = tid; i < 64 * 36; i += 256) {
            const int key = i / 36, d2 = (i % 36) * 2;
            const size_t go = ((size_t)(bh << 10) + j0 + key) * HD_ + d2;
            float2 kv = *(const float2*)&gk[go];
            __nv_bfloat16 hx = __float2bfloat16(kv.x), hy = __float2bfloat16(kv.y);
            __nv_bfloat16 lx = __float2bfloat16(kv.x - __bfloat162float(hx));
            __nv_bfloat16 ly = __float2bfloat16(kv.y - __bfloat162float(hy));
            *(uint32_t*)&Kh[key * 80 + d2] = pk(hx, hy);
            *(uint32_t*)&Kl[key * 80 + d2] = pk(lx, ly);
            float2 vv = *(const float2*)&gv[go];
            __nv_bfloat16 vhx = __float2bfloat16(vv.x), vhy = __float2bfloat16(vv.y);
            __nv_bfloat16 vlx = __float2bfloat16(vv.x - __bfloat162float(vhx));
            __nv_bfloat16 vly = __float2bfloat16(vv.y - __bfloat162float(vhy));
            Vh[d2 * 68 + key]       = vhx;
            Vh[(d2 + 1) * 68 + key] = vhy;
            Vl[d2 * 68 + key]       = vlx;
            Vl[(d2 + 1) * 68 + key] = vly;
        }
        __syncthreads();

        // ---- S = Qs . K^T  (base-2 log domain) ----
        float s[8][4];
#pragma unroll
        for (int n = 0; n < 8; n++) { s[n][0] = 0.f; s[n][1] = 0.f; s[n][2] = 0.f; s[n][3] = 0.f; }
#pragma unroll
        for (int c = 0; c < 5; c++) {
            uint32_t kb_h[8][2], kb_l[8][2];
#pragma unroll
            for (int n = 0; n < 8; n++) {
                const int base = (n * 8 + g) * 80 + c * 16 + tg;
                kb_h[n][0] = *(const uint32_t*)&Kh[base];
                kb_h[n][1] = *(const uint32_t*)&Kh[base + 8];
                kb_l[n][0] = *(const uint32_t*)&Kl[base];
                kb_l[n][1] = *(const uint32_t*)&Kl[base + 8];
            }
#pragma unroll
            for (int n = 0; n < 8; n++) {
                mma16816(s[n], qh[c], kb_h[n]);
                mma16816(s[n], qh[c], kb_l[n]);
                mma16816(s[n], ql[c], kb_h[n]);
            }
        }

        // ---- online softmax (rows g and g+8) ----
        float mx0 = s[0][0], mx1 = s[0][2];
#pragma unroll
        for (int n = 0; n < 8; n++) {
            mx0 = fmaxf(mx0, fmaxf(s[n][0], s[n][1]));
            mx1 = fmaxf(mx1, fmaxf(s[n][2], s[n][3]));
        }
        mx0 = fmaxf(mx0, __shfl_xor_sync(0xffffffffu, mx0, 1));
        mx0 = fmaxf(mx0, __shfl_xor_sync(0xffffffffu, mx0, 2));
        mx1 = fmaxf(mx1, __shfl_xor_sync(0xffffffffu, mx1, 1));
        mx1 = fmaxf(mx1, __shfl_xor_sync(0xffffffffu, mx1, 2));
        const float mn0 = fmaxf(mr0, mx0), mn1 = fmaxf(mr1, mx1);
        const float f0 = exp2p(mr0 - mn0), f1 = exp2p(mr1 - mn1);
        mr0 = mn0; mr1 = mn1;
        float sum0 = 0.f, sum1 = 0.f;
#pragma unroll
        for (int n = 0; n < 8; n++) {
            s[n][0] = exp2p(s[n][0] - mn0);
            s[n][1] = exp2p(s[n][1] - mn0);
            s[n][2] = exp2p(s[n][2] - mn1);
            s[n][3] = exp2p(s[n][3] - mn1);
            sum0 += s[n][0] + s[n][1];
            sum1 += s[n][2] + s[n][3];
        }
        lr0 = lr0 * f0 + sum0;
        lr1 = lr1 * f1 + sum1;
#pragma unroll
        for (int n = 0; n < 9; n++) {
            o[n][0] *= f0; o[n][1] *= f0; o[n][2] *= f1; o[n][3] *= f1;
        }

        // ---- O += P . V  (P frags built in registers from S) ----
#pragma unroll
        for (int c = 0; c < 4; c++) {
            __nv_bfloat16 h00 = __float2bfloat16(s[2*c][0]);
            __nv_bfloat16 h01 = __float2bfloat16(s[2*c][1]);
            __nv_bfloat16 h02 = __float2bfloat16(s[2*c][2]);
            __nv_bfloat16 h03 = __float2bfloat16(s[2*c][3]);
            __nv_bfloat16 h10 = __float2bfloat16(s[2*c+1][0]);
            __nv_bfloat16 h11 = __float2bfloat16(s[2*c+1][1]);
            __nv_bfloat16 h12 = __float2bfloat16(s[2*c+1][2]);
            __nv_bfloat16 h13 = __float2bfloat16(s[2*c+1][3]);
            uint32_t pa_h[4], pa_l[4];
            pa_h[0] = pk(h00, h01); pa_h[1] = pk(h02, h03);
            pa_h[2] = pk(h10, h11); pa_h[3] = pk(h12, h13);
            pa_l[0] = pk(__float2bfloat16(s[2*c][0]   - __bfloat162float(h00)),
                         __float2bfloat16(s[2*c][1]   - __bfloat162float(h01)));
            pa_l[1] = pk(__float2bfloat16(s[2*c][2]   - __bfloat162float(h02)),
                         __float2bfloat16(s[2*c][3]   - __bfloat162float(h03)));
            pa_l[2] = pk(__float2bfloat16(s[2*c+1][0] - __bfloat162float(h10)),
                         __float2bfloat16(s[2*c+1][1] - __bfloat162float(h11)));
            pa_l[3] = pk(__float2bfloat16(s[2*c+1][2] - __bfloat162float(h12)),
                         __float2bfloat16(s[2*c+1][3] - __bfloat162float(h13)));
#pragma unroll
            for (int n = 0; n < 9; n++) {
                uint32_t vb_h[2], vb_l[2];
                const int base = (n * 8 + g) * 68 + c * 16 + tg;
                vb_h[0] = *(const uint32_t*)&Vh[base];
                vb_h[1] = *(const uint32_t*)&Vh[base + 8];
                vb_l[0] = *(const uint32_t*)&Vl[base];
                vb_l[1] = *(const uint32_t*)&Vl[base + 8];
                mma16816(o[n], pa_h, vb_h);
                mma16816(o[n], pa_l, vb_h);
                mma16816(o[n], pa_h, vb_l);
            }
        }
        __syncthreads();
    }

    // ---- finalize: reduce l across quad, normalize, write ----
    lr0 += __shfl_xor_sync(0xffffffffu, lr0, 1);
    lr0 += __shfl_xor_sync(0xffffffffu, lr0, 2);
    lr1 += __shfl_xor_sync(0xffffffffu, lr1, 1);
    lr1 += __shfl_xor_sync(0xffffffffu, lr1, 2);
    const float inv0 = 1.f / lr0, inv1 = 1.f / lr1;
    const int row0 = q0 + w * 16 + g;
    float* dst0 = g_attn + ((size_t)((b << 10) + row0) * D_ + h * HD_);
    float* dst1 = g_attn + ((size_t)((b << 10) + row0 + 8) * D_ + h * HD_);
#pragma unroll
    for (int n = 0; n < 9; n++) {
        dst0[n * 8 + tg]     = o[n][0] * inv0;
        dst0[n * 8 + tg + 1] = o[n][1] * inv0;
        dst1[n * 8 + tg]     = o[n][2] * inv1;
        dst1[n * 8 + tg + 1] = o[n][3] * inv1;
    }
}

// ---------------------------------------------------------------------------
// Launch
// ---------------------------------------------------------------------------
extern "C" void kernel_launch(void* const* d_in, const int* in_sizes, int n_in,
                              void* d_out, int out_size)
{
    const float* hidden = (const float*)d_in[0];
    const float* cosp   = (const float*)d_in[1];
    const float* sinp   = (const float*)d_in[2];
    const float* qkv_w  = (const float*)d_in[3];
    const float* qkv_b  = (const float*)d_in[4];
    const float* proj_w = (const float*)d_in[5];
    const float* proj_b = (const float*)d_in[6];
    float* out = (float*)d_out;

    // 1) QKV GEMM (HMMA bf16-split) with scatter into [3][B][H][S][HD]
    {
        dim3 grid(N3_ / 128, M_ / 128);
        gemm_mma<1><<<grid, 256>>>(hidden, qkv_w, qkv_b, nullptr, D_, N3_);
    }
    // 2) RoPE on q and k
    {
        const int total = 2 * B_ * H_ * S_ * 36;
        rope_kernel<<<(total + 255) / 256, 256>>>(cosp, sinp);
    }
    // 3) HMMA flash attention
    {
        dim3 grid(B_ * H_, S_ / 128);
        attn_mma<<<grid, 256>>>();
    }
    // 4) Output projection (HMMA bf16-split)
    {
        dim3 grid(D_ / 128, M_ / 128);
        gemm_mma<0><<<grid, 256>>>(nullptr, proj_w, proj_b, out, D_, D_);
    }
}

// round 7
// speedup vs baseline: 2.7581x; 1.2463x over previous
#include <cuda_runtime.h>
#include <cuda_bf16.h>
#include <math.h>
#include <stdint.h>

#define B_   8
#define S_   1024
#define D_   1152
#define H_   16
#define HD_  72
#define M_   (B_*S_)          // 8192
#define N3_  (3*D_)           // 3456
#define BHSHD (B_*H_*S_*HD_)  // 9437184
#define SCL 0.170044411294f   // 72^-0.5 * log2(e)

// Scratch (device globals; no allocations allowed)
__device__ float g_qkv[3u*BHSHD];                         // fp32 [3][B][H][S][HD]
__device__ __nv_bfloat16 g_qkvh[3u*BHSHD], g_qkvl[3u*BHSHD];
__device__ __nv_bfloat16 g_attnh[(size_t)M_*D_], g_attnl[(size_t)M_*D_];
__device__ __nv_bfloat16 g_hidh[(size_t)M_*D_],  g_hidl[(size_t)M_*D_];
__device__ __nv_bfloat16 g_wqh[(size_t)N3_*D_],  g_wql[(size_t)N3_*D_];
__device__ __nv_bfloat16 g_wph[(size_t)D_*D_],   g_wpl[(size_t)D_*D_];

// ---------------------------------------------------------------------------
// helpers
// ---------------------------------------------------------------------------
__device__ __forceinline__ uint32_t pk(__nv_bfloat16 a, __nv_bfloat16 b) {
    return (uint32_t)__bfloat16_as_ushort(a) | ((uint32_t)__bfloat16_as_ushort(b) << 16);
}
__device__ __forceinline__ void cvt_hi_lo(float4 v, uint2& hi, uint2& lo) {
    __nv_bfloat16 hx = __float2bfloat16(v.x), hy = __float2bfloat16(v.y);
    __nv_bfloat16 hz = __float2bfloat16(v.z), hw = __float2bfloat16(v.w);
    __nv_bfloat16 lx = __float2bfloat16(v.x - __bfloat162float(hx));
    __nv_bfloat16 ly = __float2bfloat16(v.y - __bfloat162float(hy));
    __nv_bfloat16 lz = __float2bfloat16(v.z - __bfloat162float(hz));
    __nv_bfloat16 lw = __float2bfloat16(v.w - __bfloat162float(hw));
    hi.x = pk(hx, hy); hi.y = pk(hz, hw);
    lo.x = pk(lx, ly); lo.y = pk(lz, lw);
}
__device__ __forceinline__ void mma16816(float* c, const uint32_t* a, const uint32_t* b) {
    asm volatile(
        "mma.sync.aligned.m16n8k16.row.col.f32.bf16.bf16.f32 "
        "{%0,%1,%2,%3}, {%4,%5,%6,%7}, {%8,%9}, {%0,%1,%2,%3};"
        : "+f"(c[0]), "+f"(c[1]), "+f"(c[2]), "+f"(c[3])
        : "r"(a[0]), "r"(a[1]), "r"(a[2]), "r"(a[3]), "r"(b[0]), "r"(b[1]));
}
__device__ __forceinline__ void ldm4(uint32_t* r, uint32_t a) {
    asm volatile("ldmatrix.sync.aligned.m8n8.x4.shared.b16 {%0,%1,%2,%3}, [%4];"
        : "=r"(r[0]), "=r"(r[1]), "=r"(r[2]), "=r"(r[3]) : "r"(a));
}
__device__ __forceinline__ void ldm4t(uint32_t* r, uint32_t a) {
    asm volatile("ldmatrix.sync.aligned.m8n8.x4.trans.shared.b16 {%0,%1,%2,%3}, [%4];"
        : "=r"(r[0]), "=r"(r[1]), "=r"(r[2]), "=r"(r[3]) : "r"(a));
}
__device__ __forceinline__ void ldm2t(uint32_t* r, uint32_t a) {
    asm volatile("ldmatrix.sync.aligned.m8n8.x2.trans.shared.b16 {%0,%1}, [%2];"
        : "=r"(r[0]), "=r"(r[1]) : "r"(a));
}
__device__ __forceinline__ void cp16(uint32_t dst, const void* src) {
    asm volatile("cp.async.cg.shared.global [%0], [%1], 16;" :: "r"(dst), "l"(src));
}
#define CP_COMMIT() asm volatile("cp.async.commit_group;")
template <int N> __device__ __forceinline__ void cp_wait() {
    asm volatile("cp.async.wait_group %0;" :: "n"(N));
}
// FMA-pipe 2^x for x <= 0 (no MUFU)
__device__ __forceinline__ float exp2p(float d) {
    d = fmaxf(d, -100.f);
    const float MAGIC = 12582912.f;
    float frnd = d + MAGIC;
    int   i    = __float_as_int(frnd) - __float_as_int(MAGIC);
    float f    = d - (frnd - MAGIC);
    float y = 9.6181e-3f;
    y = fmaf(y, f, 5.54906e-2f);
    y = fmaf(y, f, 2.402265e-1f);
    y = fmaf(y, f, 6.931472e-1f);
    y = fmaf(y, f, 1.f);
    return __int_as_float(__float_as_int(y) + (i << 23));
}

// ---------------------------------------------------------------------------
// fp32 -> hi/lo bf16 converters (WHICH selects destination globals)
// ---------------------------------------------------------------------------
template <int WHICH>
__global__ void cvt_pair(const float* __restrict__ src, int n4)
{
    int i = blockIdx.x * blockDim.x + threadIdx.x;
    if (i >= n4) return;
    __nv_bfloat16* h = (WHICH == 0) ? g_hidh : (WHICH == 1) ? g_wqh : g_wph;
    __nv_bfloat16* l = (WHICH == 0) ? g_hidl : (WHICH == 1) ? g_wql : g_wpl;
    float4 v = ((const float4*)src)[i];
    uint2 hi, lo; cvt_hi_lo(v, hi, lo);
    ((uint2*)h)[i] = hi;
    ((uint2*)l)[i] = lo;
}

// ---------------------------------------------------------------------------
// bf16 HMMA GEMM with cp.async double buffering + ldmatrix.
// C[m,n] = sum_k A[m,k]*W[n,k] + bias[n].  BM=BN=128, BK=32, 256 thr, 8 warps.
// MODE 1: A=hidden, B=qkv_w, scatter fp32 into g_qkv.  MODE 0: A=attn, B=proj_w.
// smem stage: Ah|Al|Bh|Bl, each 128 x 40 bf16 (stride 40 -> conflict-free ldmatrix)
// ---------------------------------------------------------------------------
#define STG 40960   // bytes per stage: 4 arrays * 128*40*2

template <int MODE>
__global__ __launch_bounds__(256)
void gemm_bf16(const float* __restrict__ bias, float* __restrict__ C, int N)
{
    extern __shared__ __nv_bfloat16 dsm[];
    const uint32_t sb = (uint32_t)__cvta_generic_to_shared(dsm);
    const int tid = threadIdx.x, wid = tid >> 5, lane = tid & 31;
    const int bm0 = blockIdx.y * 128, bn0 = blockIdx.x * 128;
    const int wm = (wid >> 2) * 64, wn = (wid & 3) * 32;
    const int K = D_;

    const __nv_bfloat16* Ah_ = MODE ? g_hidh : g_attnh;
    const __nv_bfloat16* Al_ = MODE ? g_hidl : g_attnl;
    const __nv_bfloat16* Bh_ = MODE ? g_wqh  : g_wph;
    const __nv_bfloat16* Bl_ = MODE ? g_wql  : g_wpl;

    float acc[4][4][4];
#pragma unroll
    for (int mt = 0; mt < 4; mt++)
#pragma unroll
        for (int nt = 0; nt < 4; nt++)
#pragma unroll
            for (int r = 0; r < 4; r++) acc[mt][nt][r] = 0.f;

    // per-thread load slots: idx = tid + j*256, row = idx>>2, koff = (idx&3)*8
    const int r0 = tid >> 2, r1 = (tid + 256) >> 2;
    const int kof0 = (tid & 3) * 8;  // idx&3 identical for idx and idx+256

    auto issue = [&](int c, int s) {
        const uint32_t stb = sb + s * STG;
        const int k0 = c * 32;
        cp16(stb +         r0 * 80 + kof0 * 2, Ah_ + (size_t)(bm0 + r0) * K + k0 + kof0);
        cp16(stb +         r1 * 80 + kof0 * 2, Ah_ + (size_t)(bm0 + r1) * K + k0 + kof0);
        cp16(stb + 10240 + r0 * 80 + kof0 * 2, Al_ + (size_t)(bm0 + r0) * K + k0 + kof0);
        cp16(stb + 10240 + r1 * 80 + kof0 * 2, Al_ + (size_t)(bm0 + r1) * K + k0 + kof0);
        cp16(stb + 20480 + r0 * 80 + kof0 * 2, Bh_ + (size_t)(bn0 + r0) * K + k0 + kof0);
        cp16(stb + 20480 + r1 * 80 + kof0 * 2, Bh_ + (size_t)(bn0 + r1) * K + k0 + kof0);
        cp16(stb + 30720 + r0 * 80 + kof0 * 2, Bl_ + (size_t)(bn0 + r0) * K + k0 + kof0);
        cp16(stb + 30720 + r1 * 80 + kof0 * 2, Bl_ + (size_t)(bn0 + r1) * K + k0 + kof0);
        CP_COMMIT();
    };

    issue(0, 0);
    const int NCH = K / 32;
    for (int c = 0; c < NCH; c++) {
        const int s = c & 1;
        if (c + 1 < NCH) { issue(c + 1, s ^ 1); cp_wait<1>(); }
        else             { cp_wait<0>(); }
        __syncthreads();
        const uint32_t stb = sb + s * STG;
        const uint32_t abase = stb + ((wm + (lane & 15)) * 40 + ((lane >> 4) * 8)) * 2;
        const uint32_t bbase = stb + 20480 +
            ((wn + ((lane >> 4) * 8) + (lane & 7)) * 40 + (((lane >> 3) & 1) * 8)) * 2;
#pragma unroll
        for (int ks = 0; ks < 2; ks++) {
            uint32_t ah[4][4], al[4][4], bhf[8], blf[8];
#pragma unroll
            for (int mt = 0; mt < 4; mt++) {
                ldm4(ah[mt], abase + ks * 32 + mt * 1280);
                ldm4(al[mt], abase + ks * 32 + mt * 1280 + 10240);
            }
            ldm4(&bhf[0], bbase + ks * 32);
            ldm4(&bhf[4], bbase + ks * 32 + 1280);
            ldm4(&blf[0], bbase + ks * 32 + 10240);
            ldm4(&blf[4], bbase + ks * 32 + 10240 + 1280);
#pragma unroll
            for (int mt = 0; mt < 4; mt++)
#pragma unroll
                for (int nt = 0; nt < 4; nt++) {
                    mma16816(acc[mt][nt], ah[mt], &bhf[nt * 2]);
                    mma16816(acc[mt][nt], ah[mt], &blf[nt * 2]);
                    mma16816(acc[mt][nt], al[mt], &bhf[nt * 2]);
                }
        }
        __syncthreads();
    }

    // epilogue
    const int g = lane >> 2, tg = (lane & 3) * 2;
#pragma unroll
    for (int mt = 0; mt < 4; mt++) {
#pragma unroll
        for (int nt = 0; nt < 4; nt++) {
#pragma unroll
            for (int r = 0; r < 4; r++) {
                const int m = bm0 + wm + mt * 16 + g + (r >= 2 ? 8 : 0);
                const int n = bn0 + wn + nt * 8 + tg + (r & 1);
                const float v = acc[mt][nt][r] + bias[n];
                if (MODE == 0) {
                    C[(size_t)m * N + n] = v;
                } else {
                    const int b = m >> 10, s2 = m & 1023;
                    const int t = n / D_;
                    const int rr = n - t * D_;
                    const int h = rr / HD_;
                    const int hd = rr - h * HD_;
                    g_qkv[(((size_t)(t * B_ + b) * H_ + h) * S_ + s2) * HD_ + hd] = v;
                }
            }
        }
    }
}

// ---------------------------------------------------------------------------
// RoPE + convert: q (rope, scaled by SCL), k (rope), v (copy) -> hi/lo bf16
// ---------------------------------------------------------------------------
__global__ void rope_cvt(const float* __restrict__ cosp,
                         const float* __restrict__ sinp)
{
    const int total = 3 * B_ * H_ * S_ * 36;
    int idx = blockIdx.x * blockDim.x + threadIdx.x;
    if (idx >= total) return;
    const int i = idx % 36;
    const int row = idx / 36;             // [t][b][h][s]
    const int s = row & (S_ - 1);
    const int t = row >> 17;              // B*H*S = 131072
    const float* base = g_qkv + (size_t)row * HD_;
    float x1 = base[i], x2 = base[i + 36];
    float y1, y2;
    if (t < 2) {
        y1 = x1 * cosp[s * HD_ + i]      - x2 * sinp[s * HD_ + i];
        y2 = x2 * cosp[s * HD_ + i + 36] + x1 * sinp[s * HD_ + i + 36];
        if (t == 0) { y1 *= SCL; y2 *= SCL; }
    } else { y1 = x1; y2 = x2; }
    __nv_bfloat16 h1 = __float2bfloat16(y1);
    __nv_bfloat16 h2 = __float2bfloat16(y2);
    const size_t o1 = (size_t)row * HD_ + i, o2 = o1 + 36;
    g_qkvh[o1] = h1; g_qkvl[o1] = __float2bfloat16(y1 - __bfloat162float(h1));
    g_qkvh[o2] = h2; g_qkvl[o2] = __float2bfloat16(y2 - __bfloat162float(h2));
}

// ---------------------------------------------------------------------------
// HMMA flash attention v2: bf16 inputs, ldmatrix frags, ldmatrix.trans for V.
// CTA=(bh, 128-q tile), 256 thr, KV tiles of 64. Outputs hi/lo bf16 g_attn.
// smem: phase1 Qh[128x88]@0, Ql@11264; phase2 Kh[64x88]@0, Kl@5632,
//       Vh[64x88]@11264, Vl@16896  (all bf16 elems; 22528 total = 45056 B)
// ---------------------------------------------------------------------------
__global__ __launch_bounds__(256)
void attn2()
{
    __shared__ __nv_bfloat16 sm[22528];
    const uint32_t sb = (uint32_t)__cvta_generic_to_shared(sm);
    const int tid = threadIdx.x, w = tid >> 5, lane = tid & 31;
    const int g = lane >> 2, tg = (lane & 3) * 2;
    const int bh = blockIdx.x, q0 = blockIdx.y * 128;
    const int b = bh >> 4, h = bh & 15;

    const __nv_bfloat16* qh = g_qkvh;
    const __nv_bfloat16* ql = g_qkvl;
    const __nv_bfloat16* kh = g_qkvh + (size_t)BHSHD;
    const __nv_bfloat16* kl = g_qkvl + (size_t)BHSHD;
    const __nv_bfloat16* vh = g_qkvh + (size_t)2 * BHSHD;
    const __nv_bfloat16* vl = g_qkvl + (size_t)2 * BHSHD;

    // ---- stage Q (already SCL-scaled) ----
    for (int i = tid; i < 128 * 18; i += 256) {
        const int row = i / 18, c4 = (i % 18) * 4;
        const size_t go = ((size_t)(bh << 10) + q0 + row) * HD_ + c4;
        *(uint2*)&sm[row * 88 + c4]         = *(const uint2*)&qh[go];
        *(uint2*)&sm[11264 + row * 88 + c4] = *(const uint2*)&ql[go];
    }
    for (int i = tid; i < 128 * 4; i += 256) {  // zero pad cols 72..79
        const int row = i >> 2, c = (i & 3) * 2;
        *(uint32_t*)&sm[row * 88 + 72 + c] = 0u;
        *(uint32_t*)&sm[11264 + row * 88 + 72 + c] = 0u;
    }
    __syncthreads();

    // ---- Q frags ----
    uint32_t qfh[5][4], qfl[5][4];
    const uint32_t qbase = sb + ((w * 16 + (lane & 15)) * 88 + ((lane >> 4) * 8)) * 2;
#pragma unroll
    for (int c = 0; c < 5; c++) {
        ldm4(qfh[c], qbase + c * 32);
        ldm4(qfl[c], qbase + c * 32 + 22528);
    }
    __syncthreads();

    // ---- zero K pad cols 72..79 (once; staging never writes them) ----
    for (int i = tid; i < 64 * 4; i += 256) {
        const int row = i >> 2, c = (i & 3) * 2;
        *(uint32_t*)&sm[row * 88 + 72 + c] = 0u;
        *(uint32_t*)&sm[5632 + row * 88 + 72 + c] = 0u;
    }

    float o[9][4];
#pragma unroll
    for (int n = 0; n < 9; n++) { o[n][0] = 0.f; o[n][1] = 0.f; o[n][2] = 0.f; o[n][3] = 0.f; }
    float mr0 = -1e30f, mr1 = -1e30f, lr0 = 0.f, lr1 = 0.f;

    for (int j0 = 0; j0 < S_; j0 += 64) {
        // ---- stage K and V (straight row copies, bf16) ----
        for (int i = tid; i < 64 * 18; i += 256) {
            const int row = i / 18, c4 = (i % 18) * 4;
            const size_t go = ((size_t)(bh << 10) + j0 + row) * HD_ + c4;
            *(uint2*)&sm[row * 88 + c4]         = *(const uint2*)&kh[go];
            *(uint2*)&sm[5632 + row * 88 + c4]  = *(const uint2*)&kl[go];
            *(uint2*)&sm[11264 + row * 88 + c4] = *(const uint2*)&vh[go];
            *(uint2*)&sm[16896 + row * 88 + c4] = *(const uint2*)&vl[go];
        }
        __syncthreads();

        // ---- S = Q.K^T ----
        float s[8][4];
#pragma unroll
        for (int n = 0; n < 8; n++) { s[n][0] = 0.f; s[n][1] = 0.f; s[n][2] = 0.f; s[n][3] = 0.f; }
        const uint32_t kb0 = sb + ((((lane >> 4) * 8) + (lane & 7)) * 88 + (((lane >> 3) & 1) * 8)) * 2;
#pragma unroll
        for (int c = 0; c < 5; c++) {
#pragma unroll
            for (int ktp = 0; ktp < 4; ktp++) {
                uint32_t fh[4], fl[4];
                ldm4(fh, kb0 + c * 32 + ktp * 2816);
                ldm4(fl, kb0 + c * 32 + ktp * 2816 + 11264);
                mma16816(s[ktp * 2],     qfh[c], &fh[0]);
                mma16816(s[ktp * 2],     qfh[c], &fl[0]);
                mma16816(s[ktp * 2],     qfl[c], &fh[0]);
                mma16816(s[ktp * 2 + 1], qfh[c], &fh[2]);
                mma16816(s[ktp * 2 + 1], qfh[c], &fl[2]);
                mma16816(s[ktp * 2 + 1], qfl[c], &fh[2]);
            }
        }

        // ---- online softmax (rows g, g+8) ----
        float mx0 = s[0][0], mx1 = s[0][2];
#pragma unroll
        for (int n = 0; n < 8; n++) {
            mx0 = fmaxf(mx0, fmaxf(s[n][0], s[n][1]));
            mx1 = fmaxf(mx1, fmaxf(s[n][2], s[n][3]));
        }
        mx0 = fmaxf(mx0, __shfl_xor_sync(0xffffffffu, mx0, 1));
        mx0 = fmaxf(mx0, __shfl_xor_sync(0xffffffffu, mx0, 2));
        mx1 = fmaxf(mx1, __shfl_xor_sync(0xffffffffu, mx1, 1));
        mx1 = fmaxf(mx1, __shfl_xor_sync(0xffffffffu, mx1, 2));
        const float mn0 = fmaxf(mr0, mx0), mn1 = fmaxf(mr1, mx1);
        const float f0 = exp2p(mr0 - mn0), f1 = exp2p(mr1 - mn1);
        mr0 = mn0; mr1 = mn1;
        float sum0 = 0.f, sum1 = 0.f;
#pragma unroll
        for (int n = 0; n < 8; n++) {
            s[n][0] = exp2p(s[n][0] - mn0);
            s[n][1] = exp2p(s[n][1] - mn0);
            s[n][2] = exp2p(s[n][2] - mn1);
            s[n][3] = exp2p(s[n][3] - mn1);
            sum0 += s[n][0] + s[n][1];
            sum1 += s[n][2] + s[n][3];
        }
        lr0 = lr0 * f0 + sum0;
        lr1 = lr1 * f1 + sum1;
#pragma unroll
        for (int n = 0; n < 9; n++) {
            o[n][0] *= f0; o[n][1] *= f0; o[n][2] *= f1; o[n][3] *= f1;
        }

        // ---- O += P.V  (V frags via ldmatrix.trans from [key][d] layout) ----
#pragma unroll
        for (int c2 = 0; c2 < 4; c2++) {
            __nv_bfloat16 h00 = __float2bfloat16(s[2*c2][0]);
            __nv_bfloat16 h01 = __float2bfloat16(s[2*c2][1]);
            __nv_bfloat16 h02 = __float2bfloat16(s[2*c2][2]);
            __nv_bfloat16 h03 = __float2bfloat16(s[2*c2][3]);
            __nv_bfloat16 h10 = __float2bfloat16(s[2*c2+1][0]);
            __nv_bfloat16 h11 = __float2bfloat16(s[2*c2+1][1]);
            __nv_bfloat16 h12 = __float2bfloat16(s[2*c2+1][2]);
            __nv_bfloat16 h13 = __float2bfloat16(s[2*c2+1][3]);
            uint32_t ph[4], pl[4];
            ph[0] = pk(h00, h01); ph[1] = pk(h02, h03);
            ph[2] = pk(h10, h11); ph[3] = pk(h12, h13);
            pl[0] = pk(__float2bfloat16(s[2*c2][0]   - __bfloat162float(h00)),
                       __float2bfloat16(s[2*c2][1]   - __bfloat162float(h01)));
            pl[1] = pk(__float2bfloat16(s[2*c2][2]   - __bfloat162float(h02)),
                       __float2bfloat16(s[2*c2][3]   - __bfloat162float(h03)));
            pl[2] = pk(__float2bfloat16(s[2*c2+1][0] - __bfloat162float(h10)),
                       __float2bfloat16(s[2*c2+1][1] - __bfloat162float(h11)));
            pl[3] = pk(__float2bfloat16(s[2*c2+1][2] - __bfloat162float(h12)),
                       __float2bfloat16(s[2*c2+1][3] - __bfloat162float(h13)));

            const uint32_t vrow = sb + 22528 +
                ((c2 * 16 + ((lane >> 3) & 1) * 8 + (lane & 7)) * 88) * 2;
#pragma unroll
            for (int ntp = 0; ntp < 4; ntp++) {
                uint32_t fh[4], fl[4];
                ldm4t(fh, vrow + (2 * ntp + (lane >> 4)) * 16);
                ldm4t(fl, vrow + (2 * ntp + (lane >> 4)) * 16 + 11264);
                mma16816(o[2*ntp],     ph, &fh[0]);
                mma16816(o[2*ntp],     pl, &fh[0]);
                mma16816(o[2*ntp],     ph, &fl[0]);
                mma16816(o[2*ntp + 1], ph, &fh[2]);
                mma16816(o[2*ntp + 1], pl, &fh[2]);
                mma16816(o[2*ntp + 1], ph, &fl[2]);
            }
            uint32_t fh2[2], fl2[2];
            ldm2t(fh2, vrow + 128);            // d cols 64..71
            ldm2t(fl2, vrow + 128 + 11264);
            mma16816(o[8], ph, fh2);
            mma16816(o[8], pl, fh2);
            mma16816(o[8], ph, fl2);
        }
        __syncthreads();
    }

    // ---- finalize ----
    lr0 += __shfl_xor_sync(0xffffffffu, lr0, 1);
    lr0 += __shfl_xor_sync(0xffffffffu, lr0, 2);
    lr1 += __shfl_xor_sync(0xffffffffu, lr1, 1);
    lr1 += __shfl_xor_sync(0xffffffffu, lr1, 2);
    const float inv0 = 1.f / lr0, inv1 = 1.f / lr1;
    const int row0 = q0 + w * 16 + g;
    const size_t base0 = ((size_t)((b << 10) + row0) * D_ + h * HD_);
    const size_t base1 = base0 + (size_t)8 * D_;
#pragma unroll
    for (int n = 0; n < 9; n++) {
        float v00 = o[n][0] * inv0, v01 = o[n][1] * inv0;
        float v10 = o[n][2] * inv1, v11 = o[n][3] * inv1;
        __nv_bfloat16 a00 = __float2bfloat16(v00), a01 = __float2bfloat16(v01);
        __nv_bfloat16 a10 = __float2bfloat16(v10), a11 = __float2bfloat16(v11);
        g_attnh[base0 + n * 8 + tg]     = a00;
        g_attnh[base0 + n * 8 + tg + 1] = a01;
        g_attnh[base1 + n * 8 + tg]     = a10;
        g_attnh[base1 + n * 8 + tg + 1] = a11;
        g_attnl[base0 + n * 8 + tg]     = __float2bfloat16(v00 - __bfloat162float(a00));
        g_attnl[base0 + n * 8 + tg + 1] = __float2bfloat16(v01 - __bfloat162float(a01));
        g_attnl[base1 + n * 8 + tg]     = __float2bfloat16(v10 - __bfloat162float(a10));
        g_attnl[base1 + n * 8 + tg + 1] = __float2bfloat16(v11 - __bfloat162float(a11));
    }
}

// ---------------------------------------------------------------------------
// Launch
// ---------------------------------------------------------------------------
extern "C" void kernel_launch(void* const* d_in, const int* in_sizes, int n_in,
                              void* d_out, int out_size)
{
    const float* hidden = (const float*)d_in[0];
    const float* cosp   = (const float*)d_in[1];
    const float* sinp   = (const float*)d_in[2];
    const float* qkv_b  = (const float*)d_in[4];
    const float* proj_b = (const float*)d_in[6];
    float* out = (float*)d_out;
    const float* qkv_w  = (const float*)d_in[3];
    const float* proj_w = (const float*)d_in[5];

    cudaFuncSetAttribute(gemm_bf16<1>, cudaFuncAttributeMaxDynamicSharedMemorySize, 2 * STG);
    cudaFuncSetAttribute(gemm_bf16<0>, cudaFuncAttributeMaxDynamicSharedMemorySize, 2 * STG);

    // 0) pre-convert inputs/weights to hi/lo bf16
    cvt_pair<0><<<(M_ * D_ / 4 + 255) / 256, 256>>>(hidden, M_ * D_ / 4);
    cvt_pair<1><<<(N3_ * D_ / 4 + 255) / 256, 256>>>(qkv_w, N3_ * D_ / 4);
    cvt_pair<2><<<(D_ * D_ / 4 + 255) / 256, 256>>>(proj_w, D_ * D_ / 4);

    // 1) QKV GEMM -> scatter fp32 g_qkv
    {
        dim3 grid(N3_ / 128, M_ / 128);
        gemm_bf16<1><<<grid, 256, 2 * STG>>>(qkv_b, nullptr, N3_);
    }
    // 2) RoPE + convert q,k,v to hi/lo bf16
    {
        const int total = 3 * B_ * H_ * S_ * 36;
        rope_cvt<<<(total + 255) / 256, 256>>>(cosp, sinp);
    }
    // 3) attention -> hi/lo bf16 g_attn
    {
        dim3 grid(B_ * H_, S_ / 128);
        attn2<<<grid, 256>>>();
    }
    // 4) output projection
    {
        dim3 grid(D_ / 128, M_ / 128);
        gemm_bf16<0><<<grid, 256, 2 * STG>>>(proj_b, out, D_);
    }
}